// round 7
// baseline (speedup 1.0000x reference)
#include <cuda_runtime.h>
#include <math.h>
#include <stdint.h>

#define EMB_EDGE 512
#define EMB_RBF  16
#define EMB_CBF  16
#define EMB_TRI  64
#define EMB_BIL  64
#define E_MAX    65536
#define T_MAX    262144

// scratch (device globals: allocation-free rule)
__device__ float    g_mkt[(size_t)E_MAX * EMB_TRI];   // 16 MB
__device__ float    g_x[(size_t)E_MAX * EMB_BIL];     // 16 MB
__device__ int      g_segptr[E_MAX + 1];
// prepacked weights (tf32 bit patterns)
__device__ uint32_t g_WmT[512 * 512];
__device__ uint32_t g_WstT[64 * 512];
__device__ uint32_t g_WtsT[64 * 512];
__device__ uint2    g_WbP[8 * 16 * 8 * 32];   // [kwarp][kk][ni][lane]
__device__ uint2    g_WdP[4 * 16 * 8 * 32];   // [ct][kk][ni][lane]

__device__ __forceinline__ float silu_f(float v) {
    return v / (1.0f + __expf(-v));
}

__device__ __forceinline__ uint32_t f2tf32(float f) {
    uint32_t u;
    asm("cvt.rna.tf32.f32 %0, %1;" : "=r"(u) : "f"(f));
    return u;
}

__device__ __forceinline__ void mma_tf32(float& d0, float& d1, float& d2, float& d3,
                                         uint32_t a0, uint32_t a1, uint32_t a2, uint32_t a3,
                                         uint32_t b0, uint32_t b1)
{
    asm volatile(
        "mma.sync.aligned.m16n8k8.row.col.f32.tf32.tf32.f32 "
        "{%0,%1,%2,%3}, {%4,%5,%6,%7}, {%8,%9}, {%0,%1,%2,%3};\n"
        : "+f"(d0), "+f"(d1), "+f"(d2), "+f"(d3)
        : "r"(a0), "r"(a1), "r"(a2), "r"(a3), "r"(b0), "r"(b1));
}

#define CP_ASYNC16(dst_u32, src_ptr) \
    asm volatile("cp.async.ca.shared.global [%0], [%1], 16;" :: "r"(dst_u32), "l"(src_ptr))
#define CP_COMMIT() asm volatile("cp.async.commit_group;")
#define CP_WAIT1()  asm volatile("cp.async.wait_group 1;")
#define CP_WAIT0()  asm volatile("cp.async.wait_group 0;")

// ---------------------------------------------------------------------------
// Prepack: tf32-convert weights; W_bil and W_down into MMA B-fragment layout.
// grid = 512 blocks x 256 thr
// ---------------------------------------------------------------------------
__global__ void k_prepack(const float* __restrict__ Wm, const float* __restrict__ Wd,
                          const float* __restrict__ Ws, const float* __restrict__ Wt,
                          const float* __restrict__ Wb)
{
    const int b = blockIdx.x, tid = threadIdx.x;
    if (b < 256) {               // W_mkt: 262144 floats
        int i = (b * 256 + tid) * 4;
        float4 v = *(const float4*)(Wm + i);
        *(uint4*)(g_WmT + i) = make_uint4(f2tf32(v.x), f2tf32(v.y), f2tf32(v.z), f2tf32(v.w));
    } else if (b < 288) {        // W_st
        int i = ((b - 256) * 256 + tid) * 4;
        float4 v = *(const float4*)(Ws + i);
        *(uint4*)(g_WstT + i) = make_uint4(f2tf32(v.x), f2tf32(v.y), f2tf32(v.z), f2tf32(v.w));
    } else if (b < 320) {        // W_ts
        int i = ((b - 288) * 256 + tid) * 4;
        float4 v = *(const float4*)(Wt + i);
        *(uint4*)(g_WtsT + i) = make_uint4(f2tf32(v.x), f2tf32(v.y), f2tf32(v.z), f2tf32(v.w));
    } else if (b < 448) {        // W_bil fragments: 32768 uint2
        int e = (b - 320) * 256 + tid;
        int lane = e & 31, ni = (e >> 5) & 7, kk = (e >> 8) & 15, w = e >> 12;
        int k = w * 128 + kk * 8 + (lane & 3);
        int n = ni * 8 + (lane >> 2);
        g_WbP[e] = make_uint2(f2tf32(Wb[(size_t)k * 64 + n]),
                              f2tf32(Wb[(size_t)(k + 4) * 64 + n]));
    } else {                     // W_down fragments: 16384 uint2
        int e = (b - 448) * 256 + tid;
        int lane = e & 31, ni = (e >> 5) & 7, kk = (e >> 8) & 15, ct = e >> 12;
        int k = ct * 128 + kk * 8 + (lane & 3);
        int n = ni * 8 + (lane >> 2);
        g_WdP[e] = make_uint2(f2tf32(Wd[(size_t)k * 64 + n]),
                              f2tf32(Wd[(size_t)(k + 4) * 64 + n]));
    }
}

// ---------------------------------------------------------------------------
// Fused gemm1+gemm2 (tf32):
//   h1 = silu(m_st @ W_mkt) * (rbf @ W_rbf) * s_rbf   (stays in smem, tf32)
//   m_kt = silu(h1 @ W_down)
// One block = 128 rows. Loop ct=0..3 over h1 column tiles of 128.
// smem: mainloop double-buffer (17920 f) UNION epilogue {H[128][132] tf32,
//       rbf_s[128][17], Wr_s[16][132]} -> 21184 floats = 84736 B.
// ---------------------------------------------------------------------------
#define A_PAD 36
#define B_PAD 136
#define G1_AS (128 * A_PAD)          // 4608
#define G1_BS (32 * B_PAD)           // 4352
#define G1_STAGE (G1_AS + G1_BS)     // 8960 floats
#define H_PAD 132
#define F_H    0                     // H: 128*132 u32 = 16896
#define F_RBF  16896                 // rbf_s: 128*17 = 2176
#define F_WR   19072                 // Wr_s: 16*132 = 2112
#define G12_FLOATS 21184
#define G12_SMEM (G12_FLOATS * 4)    // 84736 B

__device__ __forceinline__ void g1_load_stage(float* As, uint32_t* Bs,
                                              const float* __restrict__ A,
                                              const uint32_t* __restrict__ B,
                                              int row0, int col0, int k0, int tid)
{
    const int a_row = tid >> 3, a_kq = (tid & 7) * 4;
    #pragma unroll
    for (int p = 0; p < 4; p++) {
        int row = a_row + p * 32;
        uint32_t d = (uint32_t)__cvta_generic_to_shared(As + row * A_PAD + a_kq);
        CP_ASYNC16(d, A + (size_t)(row0 + row) * 512 + k0 + a_kq);
    }
    const int b_r = tid >> 5, b_c = (tid & 31) * 4;
    #pragma unroll
    for (int p = 0; p < 4; p++) {
        int r = b_r + p * 8;
        uint32_t d = (uint32_t)__cvta_generic_to_shared(Bs + r * B_PAD + b_c);
        CP_ASYNC16(d, B + (size_t)(k0 + r) * 512 + col0 + b_c);
    }
}

__global__ void __launch_bounds__(256)
k_gemm12(const float* __restrict__ A, const uint32_t* __restrict__ Bm,
         const float* __restrict__ rbf, const float* __restrict__ Wr,
         const float* __restrict__ s_rbf, float* __restrict__ Cmkt, int M)
{
    extern __shared__ __align__(16) float sm[];
    const int tid  = threadIdx.x;
    const int warp = tid >> 5;
    const int lane = tid & 31;
    const int grp  = lane >> 2;
    const int thr4 = lane & 3;
    const int warp_m = warp & 3;
    const int warp_n = warp >> 2;
    const int row0 = blockIdx.x * 128;

    const float s = *s_rbf;

    float acc2[8][4];   // gemm2 accumulators: warp -> rows warp*16.., cols 0..63
    #pragma unroll
    for (int ni = 0; ni < 8; ni++)
        #pragma unroll
        for (int q = 0; q < 4; q++) acc2[ni][q] = 0.f;

    #pragma unroll 1
    for (int ct = 0; ct < 4; ct++) {
        const int col0 = ct * 128;

        float acc[2][8][4];
        #pragma unroll
        for (int mi = 0; mi < 2; mi++)
            #pragma unroll
            for (int ni = 0; ni < 8; ni++)
                #pragma unroll
                for (int q = 0; q < 4; q++) acc[mi][ni][q] = 0.f;

        // ---- gemm1 mainloop (2-stage cp.async) ----
        g1_load_stage(sm, (uint32_t*)(sm + G1_AS), A, Bm, row0, col0, 0, tid);
        CP_COMMIT();

        #pragma unroll 1
        for (int it = 0; it < 16; it++) {
            const int buf = it & 1;
            float* stage = sm + buf * G1_STAGE;
            if (it + 1 < 16) {
                float* nstage = sm + (buf ^ 1) * G1_STAGE;
                g1_load_stage(nstage, (uint32_t*)(nstage + G1_AS), A, Bm,
                              row0, col0, (it + 1) * 32, tid);
                CP_COMMIT();
                CP_WAIT1();
            } else {
                CP_WAIT0();
            }
            __syncthreads();

            const float* Asf = stage;
            const uint32_t* Bsu = (const uint32_t*)(stage + G1_AS);
            #pragma unroll
            for (int kk = 0; kk < 4; kk++) {
                const int k8 = kk * 8;
                uint32_t a[2][4], b[8][2];
                #pragma unroll
                for (int mi = 0; mi < 2; mi++) {
                    int r = warp_m * 32 + mi * 16 + grp;
                    a[mi][0] = f2tf32(Asf[(r    ) * A_PAD + k8 + thr4    ]);
                    a[mi][1] = f2tf32(Asf[(r + 8) * A_PAD + k8 + thr4    ]);
                    a[mi][2] = f2tf32(Asf[(r    ) * A_PAD + k8 + thr4 + 4]);
                    a[mi][3] = f2tf32(Asf[(r + 8) * A_PAD + k8 + thr4 + 4]);
                }
                #pragma unroll
                for (int ni = 0; ni < 8; ni++) {
                    int c = warp_n * 64 + ni * 8 + grp;
                    b[ni][0] = Bsu[(k8 + thr4    ) * B_PAD + c];
                    b[ni][1] = Bsu[(k8 + thr4 + 4) * B_PAD + c];
                }
                #pragma unroll
                for (int mi = 0; mi < 2; mi++)
                    #pragma unroll
                    for (int ni = 0; ni < 8; ni++)
                        mma_tf32(acc[mi][ni][0], acc[mi][ni][1], acc[mi][ni][2], acc[mi][ni][3],
                                 a[mi][0], a[mi][1], a[mi][2], a[mi][3],
                                 b[ni][0], b[ni][1]);
            }
            __syncthreads();
        }

        // ---- epilogue: mod = rbf @ Wr[:, col0..], h = silu(acc)*mod*s -> H (tf32) ----
        uint32_t* H = (uint32_t*)(sm + F_H);       // [128][132]
        float* rbf_s = sm + F_RBF;                  // [128][17]
        float* Wr_s  = sm + F_WR;                   // [16][132]
        {
            int r = tid >> 1, q0 = (tid & 1) * 8;
            float4 v0 = *(const float4*)(rbf + (size_t)(row0 + r) * 16 + q0);
            float4 v1 = *(const float4*)(rbf + (size_t)(row0 + r) * 16 + q0 + 4);
            rbf_s[r * 17 + q0 + 0] = v0.x; rbf_s[r * 17 + q0 + 1] = v0.y;
            rbf_s[r * 17 + q0 + 2] = v0.z; rbf_s[r * 17 + q0 + 3] = v0.w;
            rbf_s[r * 17 + q0 + 4] = v1.x; rbf_s[r * 17 + q0 + 5] = v1.y;
            rbf_s[r * 17 + q0 + 6] = v1.z; rbf_s[r * 17 + q0 + 7] = v1.w;
            int q = tid >> 4, c = (tid & 15) * 8;
            float4 w0 = *(const float4*)(Wr + (size_t)q * 512 + col0 + c);
            float4 w1 = *(const float4*)(Wr + (size_t)q * 512 + col0 + c + 4);
            *(float4*)(Wr_s + q * H_PAD + c)     = w0;
            *(float4*)(Wr_s + q * H_PAD + c + 4) = w1;
        }
        __syncthreads();

        #pragma unroll
        for (int mi = 0; mi < 2; mi++) {
            int r_lo = warp_m * 32 + mi * 16 + grp;
            int r_hi = r_lo + 8;
            float rlo[16], rhi[16];
            #pragma unroll
            for (int q = 0; q < 16; q++) {
                rlo[q] = rbf_s[r_lo * 17 + q];
                rhi[q] = rbf_s[r_hi * 17 + q];
            }
            #pragma unroll
            for (int ni = 0; ni < 8; ni++) {
                int c_s = warp_n * 64 + ni * 8 + thr4 * 2;
                float m00 = 0.f, m01 = 0.f, m10 = 0.f, m11 = 0.f;
                #pragma unroll
                for (int q = 0; q < 16; q++) {
                    float w0 = Wr_s[q * H_PAD + c_s];
                    float w1 = Wr_s[q * H_PAD + c_s + 1];
                    m00 = fmaf(rlo[q], w0, m00); m01 = fmaf(rlo[q], w1, m01);
                    m10 = fmaf(rhi[q], w0, m10); m11 = fmaf(rhi[q], w1, m11);
                }
                uint2 u_lo, u_hi;
                u_lo.x = f2tf32(silu_f(acc[mi][ni][0]) * m00 * s);
                u_lo.y = f2tf32(silu_f(acc[mi][ni][1]) * m01 * s);
                u_hi.x = f2tf32(silu_f(acc[mi][ni][2]) * m10 * s);
                u_hi.y = f2tf32(silu_f(acc[mi][ni][3]) * m11 * s);
                *(uint2*)(H + r_lo * H_PAD + c_s) = u_lo;
                *(uint2*)(H + r_hi * H_PAD + c_s) = u_hi;
            }
        }
        __syncthreads();

        // ---- gemm2 partial: acc2 += H(128x128) @ W_down[ct*128.., :] ----
        {
            const uint2* wp = g_WdP + (size_t)ct * (16 * 8 * 32) + lane;
            const int r = warp * 16 + grp;
            #pragma unroll 4
            for (int kk = 0; kk < 16; kk++) {
                const int k8 = kk * 8;
                uint32_t a0 = H[(r    ) * H_PAD + k8 + thr4    ];
                uint32_t a1 = H[(r + 8) * H_PAD + k8 + thr4    ];
                uint32_t a2 = H[(r    ) * H_PAD + k8 + thr4 + 4];
                uint32_t a3 = H[(r + 8) * H_PAD + k8 + thr4 + 4];
                #pragma unroll
                for (int ni = 0; ni < 8; ni++) {
                    uint2 bv = __ldg(wp + (kk * 8 + ni) * 32);
                    mma_tf32(acc2[ni][0], acc2[ni][1], acc2[ni][2], acc2[ni][3],
                             a0, a1, a2, a3, bv.x, bv.y);
                }
            }
        }
        __syncthreads();
    }

    // ---- write m_kt = silu(acc2) ----
    int r_lo = row0 + warp * 16 + grp;
    int r_hi = r_lo + 8;
    #pragma unroll
    for (int ni = 0; ni < 8; ni++) {
        int c = ni * 8 + thr4 * 2;
        float2 o_lo = make_float2(silu_f(acc2[ni][0]), silu_f(acc2[ni][1]));
        float2 o_hi = make_float2(silu_f(acc2[ni][2]), silu_f(acc2[ni][3]));
        *(float2*)(Cmkt + (size_t)r_lo * 64 + c) = o_lo;
        *(float2*)(Cmkt + (size_t)r_hi * 64 + c) = o_hi;
    }
}

// ---------------------------------------------------------------------------
// segment pointers
// ---------------------------------------------------------------------------
__global__ void k_segptr(const int* __restrict__ st, int Tn, int M)
{
    int e = blockIdx.x * blockDim.x + threadIdx.x;
    if (e > M) return;
    if (e == M) { g_segptr[M] = Tn; return; }
    int lo = 0, hi = Tn;
    while (lo < hi) {
        int mid = (lo + hi) >> 1;
        if (st[mid] < e) lo = mid + 1; else hi = mid;
    }
    g_segptr[e] = lo;
}

// ---------------------------------------------------------------------------
// Fused bilinear: x = (segment_sum(cbf outer m_kt[kt]) @ W_bil) * s_cbf
// ---------------------------------------------------------------------------
#define BILX_Z   (16 * 1028)
#define BILX_P   (8 * 16 * 68)
#define BILX_SMEM ((BILX_Z + BILX_P) * 4)

__global__ void __launch_bounds__(256, 2)
k_bilx(const float* __restrict__ cbf, const int* __restrict__ id3_kt,
       const float* __restrict__ s_cbf, float* __restrict__ X)
{
    extern __shared__ __align__(16) uint32_t sm_bx[];
    uint32_t* Zu = sm_bx;                    // [16][1028] tf32
    float*    Ps = (float*)(sm_bx + BILX_Z); // [8][16][68] fp32 partials

    const int tid  = threadIdx.x;
    const int warp = tid >> 5;
    const int lane = tid & 31;
    const int grp  = lane >> 2;
    const int thr4 = lane & 3;
    const int e0 = blockIdx.x * 16;

    // ---- phase 1 ----
    #pragma unroll
    for (int sub = 0; sub < 2; sub++) {
        const int eloc = warp * 2 + sub;
        const int e = e0 + eloc;
        const int t0 = g_segptr[e], t1 = g_segptr[e + 1];
        float acc[16][2];
        #pragma unroll
        for (int i = 0; i < 16; i++) { acc[i][0] = 0.f; acc[i][1] = 0.f; }

        float2 m2 = make_float2(0.f, 0.f);
        float4 cb0, cb1, cb2, cb3;
        if (t0 < t1) {
            int kt = __ldg(&id3_kt[t0]);
            m2  = *(const float2*)(g_mkt + (size_t)kt * 64 + lane * 2);
            cb0 = __ldg((const float4*)(cbf + (size_t)t0 * 16));
            cb1 = __ldg((const float4*)(cbf + (size_t)t0 * 16 + 4));
            cb2 = __ldg((const float4*)(cbf + (size_t)t0 * 16 + 8));
            cb3 = __ldg((const float4*)(cbf + (size_t)t0 * 16 + 12));
        }
        for (int t = t0; t < t1; t++) {
            float2 m2n = make_float2(0.f, 0.f);
            float4 nb0, nb1, nb2, nb3;
            if (t + 1 < t1) {
                int ktn = __ldg(&id3_kt[t + 1]);
                m2n = *(const float2*)(g_mkt + (size_t)ktn * 64 + lane * 2);
                nb0 = __ldg((const float4*)(cbf + (size_t)(t + 1) * 16));
                nb1 = __ldg((const float4*)(cbf + (size_t)(t + 1) * 16 + 4));
                nb2 = __ldg((const float4*)(cbf + (size_t)(t + 1) * 16 + 8));
                nb3 = __ldg((const float4*)(cbf + (size_t)(t + 1) * 16 + 12));
            }
            acc[ 0][0] = fmaf(cb0.x, m2.x, acc[ 0][0]); acc[ 0][1] = fmaf(cb0.x, m2.y, acc[ 0][1]);
            acc[ 1][0] = fmaf(cb0.y, m2.x, acc[ 1][0]); acc[ 1][1] = fmaf(cb0.y, m2.y, acc[ 1][1]);
            acc[ 2][0] = fmaf(cb0.z, m2.x, acc[ 2][0]); acc[ 2][1] = fmaf(cb0.z, m2.y, acc[ 2][1]);
            acc[ 3][0] = fmaf(cb0.w, m2.x, acc[ 3][0]); acc[ 3][1] = fmaf(cb0.w, m2.y, acc[ 3][1]);
            acc[ 4][0] = fmaf(cb1.x, m2.x, acc[ 4][0]); acc[ 4][1] = fmaf(cb1.x, m2.y, acc[ 4][1]);
            acc[ 5][0] = fmaf(cb1.y, m2.x, acc[ 5][0]); acc[ 5][1] = fmaf(cb1.y, m2.y, acc[ 5][1]);
            acc[ 6][0] = fmaf(cb1.z, m2.x, acc[ 6][0]); acc[ 6][1] = fmaf(cb1.z, m2.y, acc[ 6][1]);
            acc[ 7][0] = fmaf(cb1.w, m2.x, acc[ 7][0]); acc[ 7][1] = fmaf(cb1.w, m2.y, acc[ 7][1]);
            acc[ 8][0] = fmaf(cb2.x, m2.x, acc[ 8][0]); acc[ 8][1] = fmaf(cb2.x, m2.y, acc[ 8][1]);
            acc[ 9][0] = fmaf(cb2.y, m2.x, acc[ 9][0]); acc[ 9][1] = fmaf(cb2.y, m2.y, acc[ 9][1]);
            acc[10][0] = fmaf(cb2.z, m2.x, acc[10][0]); acc[10][1] = fmaf(cb2.z, m2.y, acc[10][1]);
            acc[11][0] = fmaf(cb2.w, m2.x, acc[11][0]); acc[11][1] = fmaf(cb2.w, m2.y, acc[11][1]);
            acc[12][0] = fmaf(cb3.x, m2.x, acc[12][0]); acc[12][1] = fmaf(cb3.x, m2.y, acc[12][1]);
            acc[13][0] = fmaf(cb3.y, m2.x, acc[13][0]); acc[13][1] = fmaf(cb3.y, m2.y, acc[13][1]);
            acc[14][0] = fmaf(cb3.z, m2.x, acc[14][0]); acc[14][1] = fmaf(cb3.z, m2.y, acc[14][1]);
            acc[15][0] = fmaf(cb3.w, m2.x, acc[15][0]); acc[15][1] = fmaf(cb3.w, m2.y, acc[15][1]);
            m2 = m2n; cb0 = nb0; cb1 = nb1; cb2 = nb2; cb3 = nb3;
        }
        #pragma unroll
        for (int i = 0; i < 16; i++) {
            uint2 u = make_uint2(f2tf32(acc[i][0]), f2tf32(acc[i][1]));
            *(uint2*)(Zu + eloc * 1028 + i * 64 + lane * 2) = u;
        }
    }
    __syncthreads();

    // ---- phase 2: warp w -> K slice [w*128, (w+1)*128), prepacked B ----
    {
        const int kbase = warp * 128;
        const uint2* wp = g_WbP + (size_t)warp * (16 * 8 * 32) + lane;
        float acc[8][4];
        #pragma unroll
        for (int ni = 0; ni < 8; ni++)
            #pragma unroll
            for (int q = 0; q < 4; q++) acc[ni][q] = 0.f;

        #pragma unroll 4
        for (int kk = 0; kk < 16; kk++) {
            const int k8 = kbase + kk * 8;
            uint32_t a0 = Zu[(grp    ) * 1028 + k8 + thr4    ];
            uint32_t a1 = Zu[(grp + 8) * 1028 + k8 + thr4    ];
            uint32_t a2 = Zu[(grp    ) * 1028 + k8 + thr4 + 4];
            uint32_t a3 = Zu[(grp + 8) * 1028 + k8 + thr4 + 4];
            #pragma unroll
            for (int ni = 0; ni < 8; ni++) {
                uint2 bv = __ldg(wp + (kk * 8 + ni) * 32);
                mma_tf32(acc[ni][0], acc[ni][1], acc[ni][2], acc[ni][3],
                         a0, a1, a2, a3, bv.x, bv.y);
            }
        }

        float* myP = Ps + warp * (16 * 68);
        #pragma unroll
        for (int ni = 0; ni < 8; ni++) {
            int c = ni * 8 + thr4 * 2;
            *(float2*)(myP + (grp    ) * 68 + c) = make_float2(acc[ni][0], acc[ni][1]);
            *(float2*)(myP + (grp + 8) * 68 + c) = make_float2(acc[ni][2], acc[ni][3]);
        }
    }
    __syncthreads();

    // ---- reduction ----
    {
        const int row = tid >> 4;
        const int c0  = (tid & 15) * 4;
        float4 sum = make_float4(0.f, 0.f, 0.f, 0.f);
        #pragma unroll
        for (int w = 0; w < 8; w++) {
            float4 p = *(const float4*)(Ps + w * (16 * 68) + row * 68 + c0);
            sum.x += p.x; sum.y += p.y; sum.z += p.z; sum.w += p.w;
        }
        const float sc = *s_cbf;
        sum.x *= sc; sum.y *= sc; sum.z *= sc; sum.w *= sc;
        *(float4*)(X + (size_t)(e0 + row) * 64 + c0) = sum;
    }
}

// ---------------------------------------------------------------------------
// Output (tf32): out = (silu(x@W_st) + silu(x[swap]@W_ts)) / sqrt(2)
// ---------------------------------------------------------------------------
__global__ void __launch_bounds__(256, 2)
k_out_tc(const uint32_t* __restrict__ Wst, const uint32_t* __restrict__ Wts,
         const int* __restrict__ idx_swap, const float* __restrict__ X,
         float* __restrict__ out, int M)
{
    extern __shared__ __align__(16) uint32_t sm_u[];
    uint32_t* X1s = sm_u;                 // [64][68]
    uint32_t* X2s = X1s + 64 * 68;        // [64][68]
    uint32_t* W1s = X2s + 64 * 68;        // [64][136]
    uint32_t* W2s = W1s + 64 * 136;       // [64][136]

    const int tid  = threadIdx.x;
    const int warp = tid >> 5;
    const int lane = tid & 31;
    const int grp  = lane >> 2;
    const int thr4 = lane & 3;
    const int warp_m = warp & 3;
    const int warp_n = warp >> 2;
    const int e0 = blockIdx.y * 64;
    const int col0 = blockIdx.x * 128;

    #pragma unroll
    for (int p = 0; p < 4; p++) {
        int idx = p * 256 + tid;
        int r = idx >> 4, q = (idx & 15) * 4;
        float4 v = *(const float4*)(X + (size_t)(e0 + r) * 64 + q);
        *(uint4*)(X1s + r * 68 + q) =
            make_uint4(f2tf32(v.x), f2tf32(v.y), f2tf32(v.z), f2tf32(v.w));
        int ge = __ldg(&idx_swap[e0 + r]);
        float4 g = *(const float4*)(X + (size_t)ge * 64 + q);
        *(uint4*)(X2s + r * 68 + q) =
            make_uint4(f2tf32(g.x), f2tf32(g.y), f2tf32(g.z), f2tf32(g.w));
    }
    #pragma unroll
    for (int p = 0; p < 8; p++) {
        int idx = p * 256 + tid;
        int r = idx >> 5, c4 = (idx & 31) * 4;
        *(uint4*)(W1s + r * 136 + c4) = *(const uint4*)(Wst + (size_t)r * 512 + col0 + c4);
        *(uint4*)(W2s + r * 136 + c4) = *(const uint4*)(Wts + (size_t)r * 512 + col0 + c4);
    }
    __syncthreads();

    float accA[8][4], accB[8][4];
    #pragma unroll
    for (int ni = 0; ni < 8; ni++)
        #pragma unroll
        for (int q = 0; q < 4; q++) { accA[ni][q] = 0.f; accB[ni][q] = 0.f; }

    const int rA = warp_m * 16 + grp;
    #pragma unroll
    for (int k8 = 0; k8 < 64; k8 += 8) {
        uint32_t a1[4], a2[4];
        a1[0] = X1s[(rA    ) * 68 + k8 + thr4    ];
        a1[1] = X1s[(rA + 8) * 68 + k8 + thr4    ];
        a1[2] = X1s[(rA    ) * 68 + k8 + thr4 + 4];
        a1[3] = X1s[(rA + 8) * 68 + k8 + thr4 + 4];
        a2[0] = X2s[(rA    ) * 68 + k8 + thr4    ];
        a2[1] = X2s[(rA + 8) * 68 + k8 + thr4    ];
        a2[2] = X2s[(rA    ) * 68 + k8 + thr4 + 4];
        a2[3] = X2s[(rA + 8) * 68 + k8 + thr4 + 4];
        #pragma unroll
        for (int ni = 0; ni < 8; ni++) {
            int c = warp_n * 64 + ni * 8 + grp;
            uint32_t b10 = W1s[(k8 + thr4    ) * 136 + c];
            uint32_t b11 = W1s[(k8 + thr4 + 4) * 136 + c];
            uint32_t b20 = W2s[(k8 + thr4    ) * 136 + c];
            uint32_t b21 = W2s[(k8 + thr4 + 4) * 136 + c];
            mma_tf32(accA[ni][0], accA[ni][1], accA[ni][2], accA[ni][3],
                     a1[0], a1[1], a1[2], a1[3], b10, b11);
            mma_tf32(accB[ni][0], accB[ni][1], accB[ni][2], accB[ni][3],
                     a2[0], a2[1], a2[2], a2[3], b20, b21);
        }
    }

    const float inv_sqrt2 = 0.70710678118654752f;
    int r_lo = e0 + warp_m * 16 + grp;
    int r_hi = r_lo + 8;
    #pragma unroll
    for (int ni = 0; ni < 8; ni++) {
        int c = col0 + warp_n * 64 + ni * 8 + thr4 * 2;
        float2 o_lo, o_hi;
        o_lo.x = (silu_f(accA[ni][0]) + silu_f(accB[ni][0])) * inv_sqrt2;
        o_lo.y = (silu_f(accA[ni][1]) + silu_f(accB[ni][1])) * inv_sqrt2;
        o_hi.x = (silu_f(accA[ni][2]) + silu_f(accB[ni][2])) * inv_sqrt2;
        o_hi.y = (silu_f(accA[ni][3]) + silu_f(accB[ni][3])) * inv_sqrt2;
        *(float2*)(out + (size_t)r_lo * 512 + c) = o_lo;
        *(float2*)(out + (size_t)r_hi * 512 + c) = o_hi;
    }
}

// ---------------------------------------------------------------------------
extern "C" void kernel_launch(void* const* d_in, const int* in_sizes, int n_in,
                              void* d_out, int out_size)
{
    const float* m_st     = (const float*)d_in[0];
    const float* rbf      = (const float*)d_in[1];
    const float* cbf      = (const float*)d_in[2];
    const int*   idx_swap = (const int*)  d_in[3];
    const int*   id3_kt   = (const int*)  d_in[4];
    const int*   id3_st   = (const int*)  d_in[5];
    /* d_in[6] = id3_ragged_idx (unused) */
    const float* W_mkt    = (const float*)d_in[7];
    const float* W_rbf    = (const float*)d_in[8];
    const float* W_down   = (const float*)d_in[9];
    const float* W_bil    = (const float*)d_in[10];
    const float* W_st     = (const float*)d_in[11];
    const float* W_ts     = (const float*)d_in[12];
    const float* s_rbf    = (const float*)d_in[13];
    const float* s_cbf    = (const float*)d_in[14];
    float* out = (float*)d_out;

    const int M  = in_sizes[0] / EMB_EDGE;   // 65536
    const int Tn = in_sizes[2] / EMB_CBF;    // 262144

    float *p_mkt, *p_x;
    uint32_t *p_WmT, *p_WstT, *p_WtsT;
    cudaGetSymbolAddress((void**)&p_mkt,  g_mkt);
    cudaGetSymbolAddress((void**)&p_x,    g_x);
    cudaGetSymbolAddress((void**)&p_WmT,  g_WmT);
    cudaGetSymbolAddress((void**)&p_WstT, g_WstT);
    cudaGetSymbolAddress((void**)&p_WtsT, g_WtsT);

    // 0. prepack weights (tf32 bits + fragment layouts)
    k_prepack<<<512, 256>>>(W_mkt, W_down, W_st, W_ts, W_bil);
    // 3. segment pointers (independent of prepack)
    k_segptr<<<(M + 256) / 256, 256>>>(id3_st, Tn, M);
    // 1+2 fused: m_kt = silu( (silu(m_st@W_mkt)*(rbf@W_rbf)*s) @ W_down )
    cudaFuncSetAttribute(k_gemm12, cudaFuncAttributeMaxDynamicSharedMemorySize, G12_SMEM);
    k_gemm12<<<M / 128, 256, G12_SMEM>>>(m_st, p_WmT, rbf, W_rbf, s_rbf, p_mkt, M);
    // 4+5 fused: x = (segment_sum(cbf outer m_t) @ W_bil) * s_cbf
    cudaFuncSetAttribute(k_bilx, cudaFuncAttributeMaxDynamicSharedMemorySize, BILX_SMEM);
    k_bilx<<<M / 16, 256, BILX_SMEM>>>(cbf, id3_kt, s_cbf, p_x);
    // 6. out = (silu(x@W_st) + silu(x[swap]@W_ts)) / sqrt(2)
    {
        const int smem = (2 * 64 * 68 + 2 * 64 * 136) * 4;
        cudaFuncSetAttribute(k_out_tc, cudaFuncAttributeMaxDynamicSharedMemorySize, smem);
        k_out_tc<<<dim3(4, M / 64), 256, smem>>>(p_WstT, p_WtsT, idx_swap, p_x, out, M);
    }
}